// round 1
// baseline (speedup 1.0000x reference)
#include <cuda_runtime.h>
#include <math.h>

// ---------------------------------------------------------------------------
// MiniBlock: x + attn(ln1(x)); then + mlp(ln2(.))
// B=4, T=2048, C=1024, H=16, D=64, FF=4096.  All fp32.
// ---------------------------------------------------------------------------

#define B_NUM 4
#define T_SEQ 2048
#define C_DIM 1024
#define H_NUM 16
#define D_HEAD 64
#define FF_DIM 4096
#define M_ROWS (B_NUM * T_SEQ)   // 8192

// Scratch (device globals: the sanctioned no-alloc path)
__device__ float g_xn[M_ROWS * C_DIM];
__device__ float g_q [M_ROWS * C_DIM];
__device__ float g_k [M_ROWS * C_DIM];
__device__ float g_v [M_ROWS * C_DIM];
__device__ float g_at[M_ROWS * C_DIM];
__device__ float g_x2[M_ROWS * C_DIM];
__device__ float g_h [M_ROWS * C_DIM];
__device__ float g_ff[M_ROWS * FF_DIM];

// ---------------------------------------------------------------------------
// LayerNorm: one block per row (1024 elems), 256 threads, float4.
// ---------------------------------------------------------------------------
__global__ void ln_kernel(const float* __restrict__ x, const float* __restrict__ g,
                          const float* __restrict__ b, float* __restrict__ y) {
    int row = blockIdx.x;
    int tid = threadIdx.x;
    const float4* xr = (const float4*)(x + (size_t)row * C_DIM);
    float4 v = xr[tid];
    float s = v.x + v.y + v.z + v.w;
    float q = v.x * v.x + v.y * v.y + v.z * v.z + v.w * v.w;
#pragma unroll
    for (int o = 16; o > 0; o >>= 1) {
        s += __shfl_xor_sync(0xffffffffu, s, o);
        q += __shfl_xor_sync(0xffffffffu, q, o);
    }
    __shared__ float ss[8], qs[8];
    if ((tid & 31) == 0) { ss[tid >> 5] = s; qs[tid >> 5] = q; }
    __syncthreads();
    float ts = 0.f, tq = 0.f;
#pragma unroll
    for (int i = 0; i < 8; i++) { ts += ss[i]; tq += qs[i]; }
    float mu   = ts * (1.0f / C_DIM);
    float var  = tq * (1.0f / C_DIM) - mu * mu;
    float rstd = rsqrtf(var + 1e-5f);
    float4 gg = ((const float4*)g)[tid];
    float4 bb = ((const float4*)b)[tid];
    float4 o;
    o.x = (v.x - mu) * rstd * gg.x + bb.x;
    o.y = (v.y - mu) * rstd * gg.y + bb.y;
    o.z = (v.z - mu) * rstd * gg.z + bb.z;
    o.w = (v.w - mu) * rstd * gg.w + bb.w;
    ((float4*)(y + (size_t)row * C_DIM))[tid] = o;
}

// ---------------------------------------------------------------------------
// SGEMM: C = A[M,K] @ B[K,N] (+bias)(+res)(ReLU).  128x128x8 tiles,
// 256 threads, 8x8 per thread, padded smem (conflict-free frag access).
// M,N,K all multiples of 128/8 here -> no bounds checks.
// ---------------------------------------------------------------------------
template <int RELU>
__global__ __launch_bounds__(256, 2)
void sgemm(const float* __restrict__ A, const float* __restrict__ B,
           const float* __restrict__ bias, const float* __restrict__ res,
           float* __restrict__ Cc, int Mi, int Ni, int Ki) {
    __shared__ float As[8][132];
    __shared__ float Bs[8][132];
    int tid = threadIdx.x;
    int bx = blockIdx.x, by = blockIdx.y;
    int tx = tid & 15, ty = tid >> 4;

    int aRow = tid >> 1;          // 0..127
    int aK   = (tid & 1) * 4;     // 0 or 4
    int bRow = tid >> 5;          // 0..7
    int bCol = (tid & 31) * 4;    // 0..124

    const float* Aptr = A + (size_t)(by * 128 + aRow) * Ki + aK;
    const float* Bptr = B + (size_t)bRow * Ni + (size_t)bx * 128 + bCol;

    float acc[8][8] = {};

    for (int k0 = 0; k0 < Ki; k0 += 8) {
        float4 a4 = *(const float4*)(Aptr + k0);
        float4 b4 = *(const float4*)(Bptr + (size_t)k0 * Ni);
        As[aK + 0][aRow] = a4.x; As[aK + 1][aRow] = a4.y;
        As[aK + 2][aRow] = a4.z; As[aK + 3][aRow] = a4.w;
        *(float4*)&Bs[bRow][bCol] = b4;
        __syncthreads();
#pragma unroll
        for (int k = 0; k < 8; k++) {
            float a[8], bb[8];
            *(float4*)(a)      = *(const float4*)&As[k][ty * 4];
            *(float4*)(a + 4)  = *(const float4*)&As[k][64 + ty * 4];
            *(float4*)(bb)     = *(const float4*)&Bs[k][tx * 4];
            *(float4*)(bb + 4) = *(const float4*)&Bs[k][64 + tx * 4];
#pragma unroll
            for (int i = 0; i < 8; i++)
#pragma unroll
                for (int j = 0; j < 8; j++)
                    acc[i][j] += a[i] * bb[j];
        }
        __syncthreads();
    }

#pragma unroll
    for (int i = 0; i < 8; i++) {
        int rsub = (i < 4) ? (ty * 4 + i) : (64 + ty * 4 + i - 4);
        size_t row = (size_t)(by * 128 + rsub);
#pragma unroll
        for (int half = 0; half < 2; half++) {
            int csub = half * 64 + tx * 4;
            size_t col = (size_t)bx * 128 + csub;
            float4 v4;
            v4.x = acc[i][half * 4 + 0]; v4.y = acc[i][half * 4 + 1];
            v4.z = acc[i][half * 4 + 2]; v4.w = acc[i][half * 4 + 3];
            if (bias) {
                float4 b4 = *(const float4*)(bias + col);
                v4.x += b4.x; v4.y += b4.y; v4.z += b4.z; v4.w += b4.w;
            }
            if (res) {
                float4 r4 = *(const float4*)(res + row * Ni + col);
                v4.x += r4.x; v4.y += r4.y; v4.z += r4.z; v4.w += r4.w;
            }
            if (RELU) {
                v4.x = fmaxf(v4.x, 0.f); v4.y = fmaxf(v4.y, 0.f);
                v4.z = fmaxf(v4.z, 0.f); v4.w = fmaxf(v4.w, 0.f);
            }
            *(float4*)(Cc + row * Ni + col) = v4;
        }
    }
}

// ---------------------------------------------------------------------------
// Flash attention (fp32, causal): one block per (q-tile of 64, head, batch).
// 256 threads, 4x4 per thread on the 64x64 S/O tiles. Online softmax.
// ---------------------------------------------------------------------------
struct AttnSmem {
    float Qs[64][65];   // Qs[row][d]
    float Kt[64][65];   // Kt[d][col]   (K transposed)
    float Vs[64][64];   // Vs[col][d]
    float Ssh[64][65];  // S / P tile
    float mbuf[64];
    float abuf[64];
    float lbuf[64];
};

__global__ __launch_bounds__(256, 2)
void attn_kernel(const float* __restrict__ Q, const float* __restrict__ K,
                 const float* __restrict__ V, float* __restrict__ Out) {
    extern __shared__ AttnSmem sm[];
    AttnSmem& s = sm[0];

    int qt = blockIdx.x, h = blockIdx.y, b = blockIdx.z;
    int tid = threadIdx.x;
    int tx = tid & 15, ty = tid >> 4;
    int q0 = qt * 64;

    int lrow  = tid >> 2;         // 0..63
    int dbase = (tid & 3) * 16;   // 0,16,32,48

    size_t qoff = ((size_t)(b * T_SEQ + q0 + lrow)) * C_DIM + h * D_HEAD + dbase;
#pragma unroll
    for (int i = 0; i < 16; i += 4) {
        float4 t = *(const float4*)(Q + qoff + i);
        s.Qs[lrow][dbase + i + 0] = t.x; s.Qs[lrow][dbase + i + 1] = t.y;
        s.Qs[lrow][dbase + i + 2] = t.z; s.Qs[lrow][dbase + i + 3] = t.w;
    }
    if (tid < 64) { s.mbuf[tid] = -3e30f; s.lbuf[tid] = 0.f; }
    float O[4][4] = {};
    __syncthreads();

    for (int kt = 0; kt <= qt; kt++) {
        int k0 = kt * 64;
        size_t koff = ((size_t)(b * T_SEQ + k0 + lrow)) * C_DIM + h * D_HEAD + dbase;
#pragma unroll
        for (int i = 0; i < 16; i += 4) {
            float4 t = *(const float4*)(K + koff + i);
            s.Kt[dbase + i + 0][lrow] = t.x; s.Kt[dbase + i + 1][lrow] = t.y;
            s.Kt[dbase + i + 2][lrow] = t.z; s.Kt[dbase + i + 3][lrow] = t.w;
            float4 u = *(const float4*)(V + koff + i);
            *(float4*)&s.Vs[lrow][dbase + i] = u;
        }
        __syncthreads();

        // S = Q @ K^T
        float Sv[4][4] = {};
#pragma unroll 8
        for (int d = 0; d < 64; d++) {
            float qv[4], kv[4];
#pragma unroll
            for (int i = 0; i < 4; i++) qv[i] = s.Qs[ty * 4 + i][d];
#pragma unroll
            for (int j = 0; j < 4; j++) kv[j] = s.Kt[d][tx * 4 + j];
#pragma unroll
            for (int i = 0; i < 4; i++)
#pragma unroll
                for (int j = 0; j < 4; j++)
                    Sv[i][j] += qv[i] * kv[j];
        }
        const float scale = 0.125f;  // 1/sqrt(64)
        bool diag = (kt == qt);
#pragma unroll
        for (int i = 0; i < 4; i++)
#pragma unroll
            for (int j = 0; j < 4; j++) {
                float val = Sv[i][j] * scale;
                if (diag && (tx * 4 + j) > (ty * 4 + i)) val = -3e30f;
                Sv[i][j] = val;
                s.Ssh[ty * 4 + i][tx * 4 + j] = val;
            }
        __syncthreads();

        // row max -> new m, alpha
        if (tid < 64) {
            float mo = s.mbuf[tid];
            float mn = mo;
#pragma unroll 8
            for (int c = 0; c < 64; c++) mn = fmaxf(mn, s.Ssh[tid][c]);
            s.abuf[tid] = __expf(mo - mn);
            s.mbuf[tid] = mn;
        }
        __syncthreads();

        // P = exp(S - m), rescale O
        float mn[4], al[4];
#pragma unroll
        for (int i = 0; i < 4; i++) { mn[i] = s.mbuf[ty * 4 + i]; al[i] = s.abuf[ty * 4 + i]; }
#pragma unroll
        for (int i = 0; i < 4; i++)
#pragma unroll
            for (int j = 0; j < 4; j++) {
                Sv[i][j] = __expf(Sv[i][j] - mn[i]);
                O[i][j] *= al[i];
            }
#pragma unroll
        for (int i = 0; i < 4; i++)
#pragma unroll
            for (int j = 0; j < 4; j++)
                s.Ssh[ty * 4 + i][tx * 4 + j] = Sv[i][j];
        __syncthreads();

        // l update
        if (tid < 64) {
            float acc = 0.f;
#pragma unroll 8
            for (int c = 0; c < 64; c++) acc += s.Ssh[tid][c];
            s.lbuf[tid] = s.lbuf[tid] * s.abuf[tid] + acc;
        }

        // O += P @ V
#pragma unroll 4
        for (int c = 0; c < 64; c++) {
            float pv[4];
#pragma unroll
            for (int i = 0; i < 4; i++) pv[i] = s.Ssh[ty * 4 + i][c];
            float4 vv = *(const float4*)&s.Vs[c][tx * 4];
#pragma unroll
            for (int i = 0; i < 4; i++) {
                O[i][0] += pv[i] * vv.x; O[i][1] += pv[i] * vv.y;
                O[i][2] += pv[i] * vv.z; O[i][3] += pv[i] * vv.w;
            }
        }
        __syncthreads();
    }

    float linv[4];
#pragma unroll
    for (int i = 0; i < 4; i++) linv[i] = 1.0f / s.lbuf[ty * 4 + i];
#pragma unroll
    for (int i = 0; i < 4; i++) {
        size_t row = (size_t)(b * T_SEQ + q0 + ty * 4 + i);
        float4 o4;
        o4.x = O[i][0] * linv[i]; o4.y = O[i][1] * linv[i];
        o4.z = O[i][2] * linv[i]; o4.w = O[i][3] * linv[i];
        *(float4*)(Out + row * C_DIM + h * D_HEAD + tx * 4) = o4;
    }
}

// ---------------------------------------------------------------------------
// Launch
// ---------------------------------------------------------------------------
extern "C" void kernel_launch(void* const* d_in, const int* in_sizes, int n_in,
                              void* d_out, int out_size) {
    const float* x    = (const float*)d_in[0];
    const float* Wq   = (const float*)d_in[1];
    const float* Wk   = (const float*)d_in[2];
    const float* Wv   = (const float*)d_in[3];
    const float* Wo   = (const float*)d_in[4];
    const float* bo   = (const float*)d_in[5];
    const float* ln1g = (const float*)d_in[6];
    const float* ln1b = (const float*)d_in[7];
    const float* ln2g = (const float*)d_in[8];
    const float* ln2b = (const float*)d_in[9];
    const float* W1   = (const float*)d_in[10];
    const float* b1   = (const float*)d_in[11];
    const float* W2   = (const float*)d_in[12];
    const float* b2   = (const float*)d_in[13];
    float* out = (float*)d_out;

    float *xn, *q, *k, *v, *at, *x2, *h, *ff;
    cudaGetSymbolAddress((void**)&xn, g_xn);
    cudaGetSymbolAddress((void**)&q,  g_q);
    cudaGetSymbolAddress((void**)&k,  g_k);
    cudaGetSymbolAddress((void**)&v,  g_v);
    cudaGetSymbolAddress((void**)&at, g_at);
    cudaGetSymbolAddress((void**)&x2, g_x2);
    cudaGetSymbolAddress((void**)&h,  g_h);
    cudaGetSymbolAddress((void**)&ff, g_ff);

    cudaFuncSetAttribute(attn_kernel, cudaFuncAttributeMaxDynamicSharedMemorySize,
                         (int)sizeof(AttnSmem));

    dim3 blk(256);
    dim3 gN1024(C_DIM / 128, M_ROWS / 128);   // (8, 64)
    dim3 gN4096(FF_DIM / 128, M_ROWS / 128);  // (32, 64)

    // 1. ln1(x)
    ln_kernel<<<M_ROWS, 256>>>(x, ln1g, ln1b, xn);
    // 2. Q, K, V projections
    sgemm<0><<<gN1024, blk>>>(xn, Wq, nullptr, nullptr, q, M_ROWS, C_DIM, C_DIM);
    sgemm<0><<<gN1024, blk>>>(xn, Wk, nullptr, nullptr, k, M_ROWS, C_DIM, C_DIM);
    sgemm<0><<<gN1024, blk>>>(xn, Wv, nullptr, nullptr, v, M_ROWS, C_DIM, C_DIM);
    // 3. causal flash attention
    attn_kernel<<<dim3(T_SEQ / 64, H_NUM, B_NUM), 256, sizeof(AttnSmem)>>>(q, k, v, at);
    // 4. output projection + bias + residual
    sgemm<0><<<gN1024, blk>>>(at, Wo, bo, x, x2, M_ROWS, C_DIM, C_DIM);
    // 5. ln2
    ln_kernel<<<M_ROWS, 256>>>(x2, ln2g, ln2b, h);
    // 6. MLP up + ReLU
    sgemm<1><<<gN4096, blk>>>(h, W1, b1, nullptr, ff, M_ROWS, FF_DIM, C_DIM);
    // 7. MLP down + bias + residual -> out
    sgemm<0><<<gN1024, blk>>>(ff, W2, b2, x2, out, M_ROWS, C_DIM, FF_DIM);
}

// round 3
// speedup vs baseline: 1.7070x; 1.7070x over previous
#include <cuda_runtime.h>
#include <cuda_bf16.h>
#include <math.h>
#include <cstdint>

// ---------------------------------------------------------------------------
// MiniBlock: x + attn(ln1(x)); then + mlp(ln2(.))
// B=4, T=2048, C=1024, H=16, D=64, FF=4096.
// GEMMs: mma.sync bf16 split (hi+lo, 3 products) with fp32 accumulation.
// (sm_100 base target: no tcgen05; HMMA via mma.sync.m16n8k16)
// ---------------------------------------------------------------------------

#define B_NUM 4
#define T_SEQ 2048
#define C_DIM 1024
#define H_NUM 16
#define D_HEAD 64
#define FF_DIM 4096
#define M_ROWS (B_NUM * T_SEQ)   // 8192

// ---------------- scratch (device globals; sanctioned no-alloc path) -------
__device__ float g_q [M_ROWS * C_DIM];
__device__ float g_k [M_ROWS * C_DIM];
__device__ float g_v [M_ROWS * C_DIM];
__device__ float g_at[M_ROWS * C_DIM];
__device__ float g_x2[M_ROWS * C_DIM];

__device__ __nv_bfloat16 g_ahi[M_ROWS * C_DIM];
__device__ __nv_bfloat16 g_alo[M_ROWS * C_DIM];
__device__ __nv_bfloat16 g_fhi[M_ROWS * FF_DIM];
__device__ __nv_bfloat16 g_flo[M_ROWS * FF_DIM];

__device__ __nv_bfloat16 g_wqh[C_DIM * C_DIM], g_wql[C_DIM * C_DIM];
__device__ __nv_bfloat16 g_wkh[C_DIM * C_DIM], g_wkl[C_DIM * C_DIM];
__device__ __nv_bfloat16 g_wvh[C_DIM * C_DIM], g_wvl[C_DIM * C_DIM];
__device__ __nv_bfloat16 g_woh[C_DIM * C_DIM], g_wol[C_DIM * C_DIM];
__device__ __nv_bfloat16 g_w1h[FF_DIM * C_DIM], g_w1l[FF_DIM * C_DIM];
__device__ __nv_bfloat16 g_w2h[C_DIM * FF_DIM], g_w2l[C_DIM * FF_DIM];

// ---------------- PTX helpers (sm_80-era only) ------------------------------
__device__ __forceinline__ uint32_t smem_u32(const void* p) {
    uint32_t a;
    asm("{ .reg .u64 t; cvta.to.shared.u64 t, %1; cvt.u32.u64 %0, t; }" : "=r"(a) : "l"(p));
    return a;
}
__device__ __forceinline__ void cp16(uint32_t dst, const void* src) {
    asm volatile("cp.async.cg.shared.global [%0], [%1], 16;" :: "r"(dst), "l"(src));
}
__device__ __forceinline__ void cp_commit() { asm volatile("cp.async.commit_group;" ::: "memory"); }
template <int N> __device__ __forceinline__ void cp_wait() {
    asm volatile("cp.async.wait_group %0;" :: "n"(N) : "memory");
}
__device__ __forceinline__ void ldsm4(uint32_t r[4], uint32_t addr) {
    asm volatile("ldmatrix.sync.aligned.m8n8.x4.shared.b16 {%0,%1,%2,%3}, [%4];"
                 : "=r"(r[0]), "=r"(r[1]), "=r"(r[2]), "=r"(r[3]) : "r"(addr));
}
__device__ __forceinline__ void mma_bf16(float c[4], const uint32_t a[4],
                                         uint32_t b0, uint32_t b1) {
    asm volatile(
        "mma.sync.aligned.m16n8k16.row.col.f32.bf16.bf16.f32 "
        "{%0,%1,%2,%3}, {%4,%5,%6,%7}, {%8,%9}, {%0,%1,%2,%3};"
        : "+f"(c[0]), "+f"(c[1]), "+f"(c[2]), "+f"(c[3])
        : "r"(a[0]), "r"(a[1]), "r"(a[2]), "r"(a[3]), "r"(b0), "r"(b1));
}

__device__ __forceinline__ void split1(float v, __nv_bfloat16& h, __nv_bfloat16& l) {
    h = __float2bfloat16(v);
    l = __float2bfloat16(v - __bfloat162float(h));
}

#define SWZ(x) ((x) ^ (((x) >> 3) & 0x70))

// ---------------------------------------------------------------------------
// Split-bf16 HMMA GEMM: C[M,N] = (Ahi+Alo)[M,K] @ (Bhi+Blo)^T  (B stored [N,K])
// Block tile 128x128x64, 256 threads (8 warps, 2x4), warp tile 64x32.
// 3-stage cp.async pipeline; SW128-swizzled 128B smem rows; ldmatrix feeds
// mma.sync.m16n8k16 with 3 products (hh, lh, hl) per accumulator.
// ---------------------------------------------------------------------------
static constexpr int GEMM_STAGE = 65536;           // 4 x 16KB (Ahi,Alo,Bhi,Blo)
static constexpr int GEMM_SMEM  = 3 * GEMM_STAGE;  // 196608

template <int RELU, int SPLIT>
__global__ __launch_bounds__(256, 1)
void gemm_mma(const __nv_bfloat16* __restrict__ Ahi, const __nv_bfloat16* __restrict__ Alo,
              const __nv_bfloat16* __restrict__ Bhi, const __nv_bfloat16* __restrict__ Blo,
              const float* __restrict__ bias, const float* __restrict__ res,
              float* __restrict__ C, __nv_bfloat16* __restrict__ Ohi,
              __nv_bfloat16* __restrict__ Olo, int N, int K) {
    extern __shared__ __align__(1024) char smem[];
    const uint32_t sb = smem_u32(smem);
    const int tid = threadIdx.x;
    const int lane = tid & 31;
    const int wid = tid >> 5;
    const int warp_m = wid >> 2;   // 0..1
    const int warp_n = wid & 3;    // 0..3
    const int n0 = blockIdx.x * 128;
    const int m0 = blockIdx.y * 128;

    const int nc = K >> 6;   // 64-col chunks

    // ------ gmem load setup: thread owns row tid>>1, half (tid&1) of 128B ---
    const int lrow = tid >> 1;
    const int lhalf = (tid & 1) * 64;  // byte offset within row
    const char* pa0 = (const char*)(Ahi + (size_t)(m0 + lrow) * K) + lhalf;
    const char* pa1 = (const char*)(Alo + (size_t)(m0 + lrow) * K) + lhalf;
    const char* pb0 = (const char*)(Bhi + (size_t)(n0 + lrow) * K) + lhalf;
    const char* pb1 = (const char*)(Blo + (size_t)(n0 + lrow) * K) + lhalf;

    auto issue = [&](int c) {
        uint32_t base = sb + (uint32_t)(c % 3) * GEMM_STAGE;
        size_t koff = (size_t)(c << 6) * 2;  // bytes along K
#pragma unroll
        for (int j = 0; j < 4; j++) {
            uint32_t so = SWZ((uint32_t)(lrow * 128 + lhalf + j * 16));
            cp16(base + so,         pa0 + koff + j * 16);
            cp16(base + 16384 + so, pa1 + koff + j * 16);
            cp16(base + 32768 + so, pb0 + koff + j * 16);
            cp16(base + 49152 + so, pb1 + koff + j * 16);
        }
        cp_commit();
    };

    issue(0);
    if (nc > 1) issue(1);
    if (nc > 2) issue(2);

    // ------ ldmatrix lane addressing ---------------------------------------
    const int rowA = (lane & 7) + ((lane >> 3) & 1) * 8;
    const int colA = (lane >> 4) * 16;
    const int rowB = (lane & 7) + (lane >> 4) * 8;
    const int colB = ((lane >> 3) & 1) * 16;

    float acc[4][4][4];
#pragma unroll
    for (int a = 0; a < 4; a++)
#pragma unroll
        for (int b = 0; b < 4; b++)
#pragma unroll
            for (int r = 0; r < 4; r++) acc[a][b][r] = 0.f;

    for (int c = 0; c < nc; c++) {
        if (c + 2 < nc) cp_wait<2>();
        else if (c + 1 < nc) cp_wait<1>();
        else cp_wait<0>();
        __syncthreads();

        uint32_t stb = sb + (uint32_t)(c % 3) * GEMM_STAGE;
#pragma unroll
        for (int ks = 0; ks < 4; ks++) {
            uint32_t ah[4][4], al[4][4], bh[2][4], bl[2][4];
#pragma unroll
            for (int mt = 0; mt < 4; mt++) {
                uint32_t off = (uint32_t)((warp_m * 64 + mt * 16 + rowA) * 128 + ks * 32 + colA);
                uint32_t sw = SWZ(off);
                ldsm4(ah[mt], stb + sw);
                ldsm4(al[mt], stb + 16384 + sw);
            }
#pragma unroll
            for (int np = 0; np < 2; np++) {
                uint32_t off = (uint32_t)((warp_n * 32 + np * 16 + rowB) * 128 + ks * 32 + colB);
                uint32_t sw = SWZ(off);
                ldsm4(bh[np], stb + 32768 + sw);
                ldsm4(bl[np], stb + 49152 + sw);
            }
#pragma unroll
            for (int mt = 0; mt < 4; mt++)
#pragma unroll
                for (int nt = 0; nt < 4; nt++) {
                    uint32_t b0h = bh[nt >> 1][(nt & 1) * 2], b1h = bh[nt >> 1][(nt & 1) * 2 + 1];
                    uint32_t b0l = bl[nt >> 1][(nt & 1) * 2], b1l = bl[nt >> 1][(nt & 1) * 2 + 1];
                    mma_bf16(acc[mt][nt], ah[mt], b0h, b1h);   // hi*hi
                    mma_bf16(acc[mt][nt], al[mt], b0h, b1h);   // lo*hi
                    mma_bf16(acc[mt][nt], ah[mt], b0l, b1l);   // hi*lo
                }
        }
        __syncthreads();
        if (c + 3 < nc) issue(c + 3);
    }

    // ------ epilogue -------------------------------------------------------
    const int rbase = m0 + warp_m * 64 + (lane >> 2);
    const int cbase = n0 + warp_n * 32 + (lane & 3) * 2;
#pragma unroll
    for (int mt = 0; mt < 4; mt++) {
#pragma unroll
        for (int nt = 0; nt < 4; nt++) {
            int col = cbase + nt * 8;
#pragma unroll
            for (int half = 0; half < 2; half++) {
                int row = rbase + mt * 16 + half * 8;
                float v0 = acc[mt][nt][half * 2 + 0];
                float v1 = acc[mt][nt][half * 2 + 1];
                if (bias) {
                    float2 b2 = *(const float2*)(bias + col);
                    v0 += b2.x; v1 += b2.y;
                }
                if (res) {
                    float2 r2 = *(const float2*)(res + (size_t)row * N + col);
                    v0 += r2.x; v1 += r2.y;
                }
                if (RELU) { v0 = fmaxf(v0, 0.f); v1 = fmaxf(v1, 0.f); }
                if (SPLIT) {
                    __nv_bfloat16 h0, l0, h1, l1;
                    split1(v0, h0, l0);
                    split1(v1, h1, l1);
                    *(__nv_bfloat162*)(Ohi + (size_t)row * N + col) = __halves2bfloat162(h0, h1);
                    *(__nv_bfloat162*)(Olo + (size_t)row * N + col) = __halves2bfloat162(l0, l1);
                } else {
                    float2 o2; o2.x = v0; o2.y = v1;
                    *(float2*)(C + (size_t)row * N + col) = o2;
                }
            }
        }
    }
}

// ---------------------------------------------------------------------------
// LayerNorm -> bf16 hi/lo split output. One block per row, 256 threads.
// ---------------------------------------------------------------------------
__global__ void ln_split(const float* __restrict__ x, const float* __restrict__ g,
                         const float* __restrict__ b, __nv_bfloat16* __restrict__ hi,
                         __nv_bfloat16* __restrict__ lo) {
    int row = blockIdx.x;
    int tid = threadIdx.x;
    const float4* xr = (const float4*)(x + (size_t)row * C_DIM);
    float4 v = xr[tid];
    float s = v.x + v.y + v.z + v.w;
    float q = v.x * v.x + v.y * v.y + v.z * v.z + v.w * v.w;
#pragma unroll
    for (int o = 16; o > 0; o >>= 1) {
        s += __shfl_xor_sync(0xffffffffu, s, o);
        q += __shfl_xor_sync(0xffffffffu, q, o);
    }
    __shared__ float ss[8], qs[8];
    if ((tid & 31) == 0) { ss[tid >> 5] = s; qs[tid >> 5] = q; }
    __syncthreads();
    float ts = 0.f, tq = 0.f;
#pragma unroll
    for (int i = 0; i < 8; i++) { ts += ss[i]; tq += qs[i]; }
    float mu = ts * (1.0f / C_DIM);
    float var = tq * (1.0f / C_DIM) - mu * mu;
    float rstd = rsqrtf(var + 1e-5f);
    float4 gg = ((const float4*)g)[tid];
    float4 bb = ((const float4*)b)[tid];
    float o0 = (v.x - mu) * rstd * gg.x + bb.x;
    float o1 = (v.y - mu) * rstd * gg.y + bb.y;
    float o2 = (v.z - mu) * rstd * gg.z + bb.z;
    float o3 = (v.w - mu) * rstd * gg.w + bb.w;
    __nv_bfloat16 h0, l0, h1, l1, h2, l2, h3, l3;
    split1(o0, h0, l0); split1(o1, h1, l1); split1(o2, h2, l2); split1(o3, h3, l3);
    __nv_bfloat162* ph = (__nv_bfloat162*)(hi + (size_t)row * C_DIM);
    __nv_bfloat162* pl = (__nv_bfloat162*)(lo + (size_t)row * C_DIM);
    ph[tid * 2]     = __halves2bfloat162(h0, h1);
    ph[tid * 2 + 1] = __halves2bfloat162(h2, h3);
    pl[tid * 2]     = __halves2bfloat162(l0, l1);
    pl[tid * 2 + 1] = __halves2bfloat162(l2, l3);
}

// elementwise split: fp32 -> bf16 hi/lo
__global__ void split_plain(const float* __restrict__ x, __nv_bfloat16* __restrict__ hi,
                            __nv_bfloat16* __restrict__ lo) {
    size_t i = ((size_t)blockIdx.x * blockDim.x + threadIdx.x) * 4;
    float4 v = *(const float4*)(x + i);
    __nv_bfloat16 h0, l0, h1, l1, h2, l2, h3, l3;
    split1(v.x, h0, l0); split1(v.y, h1, l1); split1(v.z, h2, l2); split1(v.w, h3, l3);
    __nv_bfloat162* ph = (__nv_bfloat162*)(hi + i);
    __nv_bfloat162* pl = (__nv_bfloat162*)(lo + i);
    ph[0] = __halves2bfloat162(h0, h1);
    ph[1] = __halves2bfloat162(h2, h3);
    pl[0] = __halves2bfloat162(l0, l1);
    pl[1] = __halves2bfloat162(l2, l3);
}

// weight transpose+split: W[K,N] -> T[N,K] (hi/lo bf16)
__global__ void wsplit_t(const float* __restrict__ W, __nv_bfloat16* __restrict__ Thi,
                         __nv_bfloat16* __restrict__ Tlo, int K, int N) {
    __shared__ float t[32][33];
    int n0 = blockIdx.x * 32, k0 = blockIdx.y * 32;
    int tx = threadIdx.x, ty = threadIdx.y;  // 32x8
#pragma unroll
    for (int i = 0; i < 32; i += 8) t[ty + i][tx] = W[(size_t)(k0 + ty + i) * N + n0 + tx];
    __syncthreads();
#pragma unroll
    for (int i = 0; i < 32; i += 8) {
        float v = t[tx][ty + i];
        __nv_bfloat16 h, l;
        split1(v, h, l);
        size_t o = (size_t)(n0 + ty + i) * K + k0 + tx;
        Thi[o] = h;
        Tlo[o] = l;
    }
}

// ---------------------------------------------------------------------------
// Flash attention (fp32, causal) — unchanged.
// ---------------------------------------------------------------------------
struct AttnSmem {
    float Qs[64][65];
    float Kt[64][65];
    float Vs[64][64];
    float Ssh[64][65];
    float mbuf[64];
    float abuf[64];
    float lbuf[64];
};

__global__ __launch_bounds__(256, 2)
void attn_kernel(const float* __restrict__ Q, const float* __restrict__ K,
                 const float* __restrict__ V, float* __restrict__ Out) {
    extern __shared__ AttnSmem sm[];
    AttnSmem& s = sm[0];

    int qt = blockIdx.x, h = blockIdx.y, b = blockIdx.z;
    int tid = threadIdx.x;
    int tx = tid & 15, ty = tid >> 4;
    int q0 = qt * 64;

    int lrow = tid >> 2;
    int dbase = (tid & 3) * 16;

    size_t qoff = ((size_t)(b * T_SEQ + q0 + lrow)) * C_DIM + h * D_HEAD + dbase;
#pragma unroll
    for (int i = 0; i < 16; i += 4) {
        float4 t = *(const float4*)(Q + qoff + i);
        s.Qs[lrow][dbase + i + 0] = t.x; s.Qs[lrow][dbase + i + 1] = t.y;
        s.Qs[lrow][dbase + i + 2] = t.z; s.Qs[lrow][dbase + i + 3] = t.w;
    }
    if (tid < 64) { s.mbuf[tid] = -3e30f; s.lbuf[tid] = 0.f; }
    float O[4][4] = {};
    __syncthreads();

    for (int kt = 0; kt <= qt; kt++) {
        int k0 = kt * 64;
        size_t koff = ((size_t)(b * T_SEQ + k0 + lrow)) * C_DIM + h * D_HEAD + dbase;
#pragma unroll
        for (int i = 0; i < 16; i += 4) {
            float4 t = *(const float4*)(K + koff + i);
            s.Kt[dbase + i + 0][lrow] = t.x; s.Kt[dbase + i + 1][lrow] = t.y;
            s.Kt[dbase + i + 2][lrow] = t.z; s.Kt[dbase + i + 3][lrow] = t.w;
            float4 u = *(const float4*)(V + koff + i);
            *(float4*)&s.Vs[lrow][dbase + i] = u;
        }
        __syncthreads();

        float Sv[4][4] = {};
#pragma unroll 8
        for (int d = 0; d < 64; d++) {
            float qv[4], kv[4];
#pragma unroll
            for (int i = 0; i < 4; i++) qv[i] = s.Qs[ty * 4 + i][d];
#pragma unroll
            for (int j = 0; j < 4; j++) kv[j] = s.Kt[d][tx * 4 + j];
#pragma unroll
            for (int i = 0; i < 4; i++)
#pragma unroll
                for (int j = 0; j < 4; j++)
                    Sv[i][j] += qv[i] * kv[j];
        }
        const float scale = 0.125f;
        bool diag = (kt == qt);
#pragma unroll
        for (int i = 0; i < 4; i++)
#pragma unroll
            for (int j = 0; j < 4; j++) {
                float val = Sv[i][j] * scale;
                if (diag && (tx * 4 + j) > (ty * 4 + i)) val = -3e30f;
                Sv[i][j] = val;
                s.Ssh[ty * 4 + i][tx * 4 + j] = val;
            }
        __syncthreads();

        if (tid < 64) {
            float mo = s.mbuf[tid];
            float mn = mo;
#pragma unroll 8
            for (int c = 0; c < 64; c++) mn = fmaxf(mn, s.Ssh[tid][c]);
            s.abuf[tid] = __expf(mo - mn);
            s.mbuf[tid] = mn;
        }
        __syncthreads();

        float mn[4], al[4];
#pragma unroll
        for (int i = 0; i < 4; i++) { mn[i] = s.mbuf[ty * 4 + i]; al[i] = s.abuf[ty * 4 + i]; }
#pragma unroll
        for (int i = 0; i < 4; i++)
#pragma unroll
            for (int j = 0; j < 4; j++) {
                Sv[i][j] = __expf(Sv[i][j] - mn[i]);
                O[i][j] *= al[i];
            }
#pragma unroll
        for (int i = 0; i < 4; i++)
#pragma unroll
            for (int j = 0; j < 4; j++)
                s.Ssh[ty * 4 + i][tx * 4 + j] = Sv[i][j];
        __syncthreads();

        if (tid < 64) {
            float acc = 0.f;
#pragma unroll 8
            for (int c = 0; c < 64; c++) acc += s.Ssh[tid][c];
            s.lbuf[tid] = s.lbuf[tid] * s.abuf[tid] + acc;
        }

#pragma unroll 4
        for (int c = 0; c < 64; c++) {
            float pv[4];
#pragma unroll
            for (int i = 0; i < 4; i++) pv[i] = s.Ssh[ty * 4 + i][c];
            float4 vv = *(const float4*)&s.Vs[c][tx * 4];
#pragma unroll
            for (int i = 0; i < 4; i++) {
                O[i][0] += pv[i] * vv.x; O[i][1] += pv[i] * vv.y;
                O[i][2] += pv[i] * vv.z; O[i][3] += pv[i] * vv.w;
            }
        }
        __syncthreads();
    }

    float linv[4];
#pragma unroll
    for (int i = 0; i < 4; i++) linv[i] = 1.0f / s.lbuf[ty * 4 + i];
#pragma unroll
    for (int i = 0; i < 4; i++) {
        size_t row = (size_t)(b * T_SEQ + q0 + ty * 4 + i);
        float4 o4;
        o4.x = O[i][0] * linv[i]; o4.y = O[i][1] * linv[i];
        o4.z = O[i][2] * linv[i]; o4.w = O[i][3] * linv[i];
        *(float4*)(Out + row * C_DIM + h * D_HEAD + tx * 4) = o4;
    }
}

// ---------------------------------------------------------------------------
// Launch
// ---------------------------------------------------------------------------
extern "C" void kernel_launch(void* const* d_in, const int* in_sizes, int n_in,
                              void* d_out, int out_size) {
    const float* x    = (const float*)d_in[0];
    const float* Wq   = (const float*)d_in[1];
    const float* Wk   = (const float*)d_in[2];
    const float* Wv   = (const float*)d_in[3];
    const float* Wo   = (const float*)d_in[4];
    const float* bo   = (const float*)d_in[5];
    const float* ln1g = (const float*)d_in[6];
    const float* ln1b = (const float*)d_in[7];
    const float* ln2g = (const float*)d_in[8];
    const float* ln2b = (const float*)d_in[9];
    const float* W1   = (const float*)d_in[10];
    const float* b1   = (const float*)d_in[11];
    const float* W2   = (const float*)d_in[12];
    const float* b2   = (const float*)d_in[13];
    float* out = (float*)d_out;

    float *q, *k, *v, *at, *x2;
    __nv_bfloat16 *ahi, *alo, *fhi, *flo;
    __nv_bfloat16 *wqh, *wql, *wkh, *wkl, *wvh, *wvl, *woh, *wol, *w1h, *w1l, *w2h, *w2l;
    cudaGetSymbolAddress((void**)&q,   g_q);
    cudaGetSymbolAddress((void**)&k,   g_k);
    cudaGetSymbolAddress((void**)&v,   g_v);
    cudaGetSymbolAddress((void**)&at,  g_at);
    cudaGetSymbolAddress((void**)&x2,  g_x2);
    cudaGetSymbolAddress((void**)&ahi, g_ahi);
    cudaGetSymbolAddress((void**)&alo, g_alo);
    cudaGetSymbolAddress((void**)&fhi, g_fhi);
    cudaGetSymbolAddress((void**)&flo, g_flo);
    cudaGetSymbolAddress((void**)&wqh, g_wqh); cudaGetSymbolAddress((void**)&wql, g_wql);
    cudaGetSymbolAddress((void**)&wkh, g_wkh); cudaGetSymbolAddress((void**)&wkl, g_wkl);
    cudaGetSymbolAddress((void**)&wvh, g_wvh); cudaGetSymbolAddress((void**)&wvl, g_wvl);
    cudaGetSymbolAddress((void**)&woh, g_woh); cudaGetSymbolAddress((void**)&wol, g_wol);
    cudaGetSymbolAddress((void**)&w1h, g_w1h); cudaGetSymbolAddress((void**)&w1l, g_w1l);
    cudaGetSymbolAddress((void**)&w2h, g_w2h); cudaGetSymbolAddress((void**)&w2l, g_w2l);

    cudaFuncSetAttribute(attn_kernel, cudaFuncAttributeMaxDynamicSharedMemorySize,
                         (int)sizeof(AttnSmem));
    cudaFuncSetAttribute(gemm_mma<0, 0>, cudaFuncAttributeMaxDynamicSharedMemorySize, GEMM_SMEM);
    cudaFuncSetAttribute(gemm_mma<1, 1>, cudaFuncAttributeMaxDynamicSharedMemorySize, GEMM_SMEM);

    dim3 wblk(32, 8);

    // weight transpose + split
    wsplit_t<<<dim3(C_DIM / 32, C_DIM / 32), wblk>>>(Wq, wqh, wql, C_DIM, C_DIM);
    wsplit_t<<<dim3(C_DIM / 32, C_DIM / 32), wblk>>>(Wk, wkh, wkl, C_DIM, C_DIM);
    wsplit_t<<<dim3(C_DIM / 32, C_DIM / 32), wblk>>>(Wv, wvh, wvl, C_DIM, C_DIM);
    wsplit_t<<<dim3(C_DIM / 32, C_DIM / 32), wblk>>>(Wo, woh, wol, C_DIM, C_DIM);
    wsplit_t<<<dim3(FF_DIM / 32, C_DIM / 32), wblk>>>(W1, w1h, w1l, C_DIM, FF_DIM);
    wsplit_t<<<dim3(C_DIM / 32, FF_DIM / 32), wblk>>>(W2, w2h, w2l, FF_DIM, C_DIM);

    // ln1 -> split activations
    ln_split<<<M_ROWS, 256>>>(x, ln1g, ln1b, ahi, alo);

    // Q, K, V projections
    dim3 g1024(C_DIM / 128, M_ROWS / 128);
    gemm_mma<0, 0><<<g1024, 256, GEMM_SMEM>>>(ahi, alo, wqh, wql, nullptr, nullptr,
                                              q, nullptr, nullptr, C_DIM, C_DIM);
    gemm_mma<0, 0><<<g1024, 256, GEMM_SMEM>>>(ahi, alo, wkh, wkl, nullptr, nullptr,
                                              k, nullptr, nullptr, C_DIM, C_DIM);
    gemm_mma<0, 0><<<g1024, 256, GEMM_SMEM>>>(ahi, alo, wvh, wvl, nullptr, nullptr,
                                              v, nullptr, nullptr, C_DIM, C_DIM);

    // causal flash attention
    attn_kernel<<<dim3(T_SEQ / 64, H_NUM, B_NUM), 256, sizeof(AttnSmem)>>>(q, k, v, at);

    // split attention output, then Wo projection + bias + residual -> x2
    split_plain<<<(M_ROWS * C_DIM) / (256 * 4), 256>>>(at, ahi, alo);
    gemm_mma<0, 0><<<g1024, 256, GEMM_SMEM>>>(ahi, alo, woh, wol, bo, x,
                                              x2, nullptr, nullptr, C_DIM, C_DIM);

    // ln2 -> split
    ln_split<<<M_ROWS, 256>>>(x2, ln2g, ln2b, ahi, alo);

    // MLP up + ReLU (bf16-split output straight to ff buffers)
    dim3 g4096(FF_DIM / 128, M_ROWS / 128);
    gemm_mma<1, 1><<<g4096, 256, GEMM_SMEM>>>(ahi, alo, w1h, w1l, b1, nullptr,
                                              nullptr, fhi, flo, FF_DIM, C_DIM);

    // MLP down + bias + residual -> out
    gemm_mma<0, 0><<<g1024, 256, GEMM_SMEM>>>(fhi, flo, w2h, w2l, b2, x2,
                                              out, nullptr, nullptr, C_DIM, FF_DIM);
}